// round 1
// baseline (speedup 1.0000x reference)
#include <cuda_runtime.h>
#include <math.h>
#include <float.h>

// Problem constants (fixed by the dataset)
#define NROWS 16384   // B*K = 256*64
#define D_IN  256
#define DB    512
#define NC    1024
#define KTOP  8
#define TEMP  0.1f

// ---------------- scratch (static device globals; no allocation) -------------
__device__ float g_z[(size_t)NROWS * DB];    // 32 MB  projected slots
__device__ float g_S[(size_t)NROWS * NC];    // 64 MB  z @ embed^T
__device__ float g_enorm[NC];
__device__ float g_usage[NC];
__device__ float g_vq;

// ---------------- init: code norms + zero accumulators -----------------------
__global__ void init_kernel(const float* __restrict__ embed) {
    int w = threadIdx.x >> 5, lane = threadIdx.x & 31;
    int code = blockIdx.x * 8 + w;
    if (code < NC) {
        const float* e = embed + (size_t)code * DB;
        float s = 0.f;
        #pragma unroll
        for (int i = lane; i < DB; i += 32) { float v = e[i]; s += v * v; }
        #pragma unroll
        for (int o = 16; o; o >>= 1) s += __shfl_down_sync(0xffffffffu, s, o);
        if (lane == 0) g_enorm[code] = s;
    }
    if (blockIdx.x == 0) {
        for (int i = threadIdx.x; i < NC; i += blockDim.x) g_usage[i] = 0.f;
        if (threadIdx.x == 0) g_vq = 0.f;
    }
}

// ---------------- FP32 tiled GEMM: C[M,N] = A[M,K] * B (+bias) ---------------
// bt==0: B is [K,N] row-major.  bt==1: B is [N,K] row-major (C = A * B^T).
// BM=BN=64, BK=16, 256 threads, 4x4 per-thread tile. M,N,K multiples of 64/16.
__global__ void __launch_bounds__(256)
gemm_tiled(const float* __restrict__ A, const float* __restrict__ B,
           const float* __restrict__ bias, float* __restrict__ C,
           int M, int N, int K, int bt) {
    __shared__ float As[16][65];   // padded: transposed A tile
    __shared__ float Bs[16][64];

    int tid  = threadIdx.x;
    int row0 = blockIdx.y * 64;
    int col0 = blockIdx.x * 64;
    int ty   = tid >> 4;      // 0..15
    int tx   = tid & 15;      // 0..15

    float acc[4][4];
    #pragma unroll
    for (int i = 0; i < 4; i++)
        #pragma unroll
        for (int j = 0; j < 4; j++) acc[i][j] = 0.f;

    int arow = tid >> 2;          // 0..63
    int akc  = (tid & 3) * 4;     // 0,4,8,12

    for (int k0 = 0; k0 < K; k0 += 16) {
        // A tile: 64 rows x 16 k, stored transposed
        float4 av = *reinterpret_cast<const float4*>(
            &A[(size_t)(row0 + arow) * K + k0 + akc]);
        As[akc + 0][arow] = av.x; As[akc + 1][arow] = av.y;
        As[akc + 2][arow] = av.z; As[akc + 3][arow] = av.w;

        if (!bt) {
            int bk = tid >> 4;          // 0..15
            int bc = (tid & 15) * 4;    // 0..60
            float4 bv = *reinterpret_cast<const float4*>(
                &B[(size_t)(k0 + bk) * N + col0 + bc]);
            *reinterpret_cast<float4*>(&Bs[bk][bc]) = bv;
        } else {
            int bcol = tid >> 2;        // 0..63
            int bkc  = (tid & 3) * 4;
            float4 bv = *reinterpret_cast<const float4*>(
                &B[(size_t)(col0 + bcol) * K + k0 + bkc]);
            Bs[bkc + 0][bcol] = bv.x; Bs[bkc + 1][bcol] = bv.y;
            Bs[bkc + 2][bcol] = bv.z; Bs[bkc + 3][bcol] = bv.w;
        }
        __syncthreads();

        #pragma unroll
        for (int k = 0; k < 16; k++) {
            float a0 = As[k][ty * 4 + 0];
            float a1 = As[k][ty * 4 + 1];
            float a2 = As[k][ty * 4 + 2];
            float a3 = As[k][ty * 4 + 3];
            float4 b = *reinterpret_cast<const float4*>(&Bs[k][tx * 4]);
            acc[0][0] += a0 * b.x; acc[0][1] += a0 * b.y; acc[0][2] += a0 * b.z; acc[0][3] += a0 * b.w;
            acc[1][0] += a1 * b.x; acc[1][1] += a1 * b.y; acc[1][2] += a1 * b.z; acc[1][3] += a1 * b.w;
            acc[2][0] += a2 * b.x; acc[2][1] += a2 * b.y; acc[2][2] += a2 * b.z; acc[2][3] += a2 * b.w;
            acc[3][0] += a3 * b.x; acc[3][1] += a3 * b.y; acc[3][2] += a3 * b.z; acc[3][3] += a3 * b.w;
        }
        __syncthreads();
    }

    #pragma unroll
    for (int i = 0; i < 4; i++) {
        float4 o;
        o.x = acc[i][0]; o.y = acc[i][1]; o.z = acc[i][2]; o.w = acc[i][3];
        if (bias) {
            o.x += bias[col0 + tx * 4 + 0];
            o.y += bias[col0 + tx * 4 + 1];
            o.z += bias[col0 + tx * 4 + 2];
            o.w += bias[col0 + tx * 4 + 3];
        }
        *reinterpret_cast<float4*>(
            &C[(size_t)(row0 + ty * 4 + i) * N + col0 + tx * 4]) = o;
    }
}

// ---------------- per-row: top-8, softmax, gather, reductions -----------------
// One warp per row; 8 warps per block.
__global__ void __launch_bounds__(256)
topk_kernel(const float* __restrict__ embed, float* __restrict__ out) {
    int w = threadIdx.x >> 5, lane = threadIdx.x & 31;
    int r = blockIdx.x * 8 + w;

    // load z row, compute ||z||^2
    const float* zr = g_z + (size_t)r * DB;
    float zreg[16];
    float zn = 0.f;
    #pragma unroll
    for (int i = 0; i < 16; i++) {
        float v = zr[lane + 32 * i];
        zreg[i] = v;
        zn += v * v;
    }
    #pragma unroll
    for (int o = 16; o; o >>= 1) zn += __shfl_xor_sync(0xffffffffu, zn, o);

    // per-lane sorted top-8 over d2 (ascending); scan 32 codes per lane
    float td[KTOP]; int ti[KTOP];
    #pragma unroll
    for (int j = 0; j < KTOP; j++) { td[j] = FLT_MAX; ti[j] = 0x7fffffff; }

    const float* Sr = g_S + (size_t)r * NC;
    for (int c = lane; c < NC; c += 32) {
        float d2 = zn + g_enorm[c] - 2.f * Sr[c];
        if (d2 < td[KTOP - 1]) {
            float dv = d2; int iv = c;
            #pragma unroll
            for (int j = KTOP - 1; j >= 0; j--) {
                bool shift = (j > 0) && (td[j - 1] > dv);
                if (shift) { td[j] = td[j - 1]; ti[j] = ti[j - 1]; }
                else       { td[j] = dv; ti[j] = iv; break; }
            }
        }
    }

    // warp merge: 8 rounds of argmin (tie-break: smaller code index, like jax)
    float sel_d[KTOP]; int sel_i[KTOP];
    int pos = 0;
    #pragma unroll
    for (int j = 0; j < KTOP; j++) {
        float cd = (pos < KTOP) ? td[pos] : FLT_MAX;
        int   ci = (pos < KTOP) ? ti[pos] : 0x7fffffff;
        float bd = cd; int bi = ci; int bl = lane;
        #pragma unroll
        for (int o = 16; o; o >>= 1) {
            float od = __shfl_xor_sync(0xffffffffu, bd, o);
            int   oi = __shfl_xor_sync(0xffffffffu, bi, o);
            int   ol = __shfl_xor_sync(0xffffffffu, bl, o);
            if (od < bd || (od == bd && oi < bi)) { bd = od; bi = oi; bl = ol; }
        }
        sel_d[j] = bd; sel_i[j] = bi;
        if (lane == bl) pos++;
    }

    // softmax over sqrt(d2) with temperature (sel_d[0] is the min)
    float wj[KTOP];
    float vmin = sqrtf(fmaxf(sel_d[0], 0.f));
    float wsum = 0.f;
    #pragma unroll
    for (int j = 0; j < KTOP; j++) {
        float v = sqrtf(fmaxf(sel_d[j], 0.f));
        wj[j] = expf(-(v - vmin) / TEMP);
        wsum += wj[j];
    }
    float inv = 1.f / wsum;
    #pragma unroll
    for (int j = 0; j < KTOP; j++) wj[j] *= inv;

    // q = sum_j w_j * embed[idx_j], vq partial
    float vql = 0.f;
    #pragma unroll
    for (int i = 0; i < 16; i++) {
        int col = lane + 32 * i;
        float acc = 0.f;
        #pragma unroll
        for (int j = 0; j < KTOP; j++)
            acc += wj[j] * embed[(size_t)sel_i[j] * DB + col];
        out[(size_t)r * DB + col] = acc;
        float diff = zreg[i] - acc;
        vql += diff * diff;
    }
    #pragma unroll
    for (int o = 16; o; o >>= 1) vql += __shfl_down_sync(0xffffffffu, vql, o);
    if (lane == 0) atomicAdd(&g_vq, vql);
    if (lane < KTOP) atomicAdd(&g_usage[sel_i[lane]], wj[lane]);
    if (lane == 0) out[(size_t)NROWS * DB + r] = (float)sel_i[0];
}

// ---------------- finalize scalars --------------------------------------------
__global__ void finalize_kernel(float* __restrict__ out) {
    __shared__ float sh[256];
    float s = 0.f;
    for (int c = threadIdx.x; c < NC; c += 256) {
        float u = g_usage[c] * (1.f / (float)NROWS);
        s += u * logf(u + 1e-8f);
    }
    sh[threadIdx.x] = s;
    __syncthreads();
    for (int o = 128; o; o >>= 1) {
        if (threadIdx.x < o) sh[threadIdx.x] += sh[threadIdx.x + o];
        __syncthreads();
    }
    if (threadIdx.x == 0) {
        size_t base = (size_t)NROWS * DB + NROWS;
        out[base + 0] = g_vq * (1.f / (float)((size_t)NROWS * DB));  // vq_loss
        out[base + 1] = -sh[0];                                       // entropy
    }
}

// ---------------- launch --------------------------------------------------------
extern "C" void kernel_launch(void* const* d_in, const int* in_sizes, int n_in,
                              void* d_out, int out_size) {
    const float* slots = (const float*)d_in[0];   // [256,64,256] -> [16384,256]
    const float* W     = (const float*)d_in[1];   // [256,512]
    const float* bias  = (const float*)d_in[2];   // [512]
    const float* embed = (const float*)d_in[3];   // [1024,512]
    float* out = (float*)d_out;

    float *zp = nullptr, *Sp = nullptr;
    cudaGetSymbolAddress((void**)&zp, g_z);
    cudaGetSymbolAddress((void**)&Sp, g_S);

    init_kernel<<<128, 256>>>(embed);

    // z = slots @ W + b   [16384,512]
    dim3 g1(DB / 64, NROWS / 64);
    gemm_tiled<<<g1, 256>>>(slots, W, bias, zp, NROWS, DB, D_IN, 0);

    // S = z @ embed^T     [16384,1024]
    dim3 g2(NC / 64, NROWS / 64);
    gemm_tiled<<<g2, 256>>>(zp, embed, nullptr, Sp, NROWS, NC, DB, 1);

    topk_kernel<<<NROWS / 8, 256>>>(embed, out);
    finalize_kernel<<<1, 256>>>(out);
}

// round 4
// speedup vs baseline: 1.1525x; 1.1525x over previous
#include <cuda_runtime.h>
#include <cuda_bf16.h>
#include <math.h>
#include <float.h>
#include <stdint.h>

// Problem constants (fixed by the dataset)
#define NROWS 16384   // B*K = 256*64
#define D_IN  256
#define DB    512
#define NC    1024
#define KTOP  8
#define KSEL  12      // refine candidates
#define TEMP  0.1f

// ---------------- scratch (static device globals; no allocation) -------------
// GEMM1 (z = slots@W) uses a 3-way split, 6 product terms -> K' = 6*256 = 1536
//   A' blocks: [hi, hi, mid, hi, mid, lo]
//   B' blocks: [hi, mid, hi, lo, mid, hi]
// GEMM2 (S = z@E^T) uses a 2-way split, 3 product terms -> K' = 3*512 = 1536
//   A' blocks: [z_hi, z_hi, z_lo], B' blocks: [e_hi, e_lo, e_hi]
__device__ __align__(1024) __nv_bfloat16 g_as[(size_t)NROWS * 1536];
__device__ __align__(1024) __nv_bfloat16 g_wb[(size_t)DB * 1536];
__device__ __align__(1024) __nv_bfloat16 g_zs[(size_t)NROWS * 1536];
__device__ __align__(1024) __nv_bfloat16 g_eb[(size_t)NC * 1536];
__device__ __align__(1024) float g_z[(size_t)NROWS * DB];   // fp32 z (fp32-faithful)
__device__ __align__(1024) float g_S[(size_t)NROWS * NC];   // approx z @ E^T
__device__ float g_enorm[NC];
__device__ float g_usage[NC];
__device__ float g_vq;

// ---------------- helpers -----------------------------------------------------
__device__ __forceinline__ void cp16(void* dst, const void* src) {
    uint32_t d = (uint32_t)__cvta_generic_to_shared(dst);
    asm volatile("cp.async.cg.shared.global [%0], [%1], 16;" :: "r"(d), "l"(src));
}
__device__ __forceinline__ void cp_commit() {
    asm volatile("cp.async.commit_group;" ::: "memory");
}
__device__ __forceinline__ void split2(float v, __nv_bfloat16& hi, __nv_bfloat16& lo) {
    hi = __float2bfloat16(v);
    lo = __float2bfloat16(v - __bfloat162float(hi));
}
__device__ __forceinline__ void split3(float v, __nv_bfloat16& hi, __nv_bfloat16& mid,
                                       __nv_bfloat16& lo) {
    hi = __float2bfloat16(v);
    float r1 = v - __bfloat162float(hi);
    mid = __float2bfloat16(r1);
    lo = __float2bfloat16(r1 - __bfloat162float(mid));
}
__device__ __forceinline__ void mma16816(float* c, const uint32_t* a,
                                         uint32_t b0, uint32_t b1) {
    asm volatile(
        "mma.sync.aligned.m16n8k16.row.col.f32.bf16.bf16.f32 "
        "{%0,%1,%2,%3}, {%4,%5,%6,%7}, {%8,%9}, {%0,%1,%2,%3};"
        : "+f"(c[0]), "+f"(c[1]), "+f"(c[2]), "+f"(c[3])
        : "r"(a[0]), "r"(a[1]), "r"(a[2]), "r"(a[3]), "r"(b0), "r"(b1));
}

// ---------------- pre-kernels: splits + norms ---------------------------------
__global__ void split_slots_kernel(const float* __restrict__ slots) {
    int idx = blockIdx.x * 256 + threadIdx.x;       // < NROWS*D_IN
    int row = idx >> 8, k = idx & 255;
    __nv_bfloat16 hi, mid, lo;
    split3(slots[idx], hi, mid, lo);
    __nv_bfloat16* dst = g_as + (size_t)row * 1536;
    dst[k] = hi;  dst[256 + k] = hi;  dst[512 + k] = mid;
    dst[768 + k] = hi;  dst[1024 + k] = mid;  dst[1280 + k] = lo;
}

__global__ void split_w_kernel(const float* __restrict__ W) {
    int idx = blockIdx.x * 256 + threadIdx.x;       // < D_IN*DB
    int k = idx >> 9, n = idx & 511;                // W[k,n] row-major
    __nv_bfloat16 hi, mid, lo;
    split3(W[idx], hi, mid, lo);
    __nv_bfloat16* dst = g_wb + (size_t)n * 1536;
    dst[k] = hi;  dst[256 + k] = mid;  dst[512 + k] = hi;
    dst[768 + k] = lo;  dst[1024 + k] = mid;  dst[1280 + k] = hi;
}

__global__ void init_kernel(const float* __restrict__ embed) {
    int w = threadIdx.x >> 5, lane = threadIdx.x & 31;
    int code = blockIdx.x * 8 + w;
    if (code < NC) {
        const float* e = embed + (size_t)code * DB;
        __nv_bfloat16* dst = g_eb + (size_t)code * 1536;
        float s = 0.f;
        #pragma unroll
        for (int i = lane; i < DB; i += 32) {
            float v = e[i];
            s += v * v;
            __nv_bfloat16 hi, lo;
            split2(v, hi, lo);
            dst[i] = hi; dst[512 + i] = lo; dst[1024 + i] = hi;
        }
        #pragma unroll
        for (int o = 16; o; o >>= 1) s += __shfl_down_sync(0xffffffffu, s, o);
        if (lane == 0) g_enorm[code] = s;
    }
    if (blockIdx.x == 0) {
        for (int i = threadIdx.x; i < NC; i += blockDim.x) g_usage[i] = 0.f;
        if (threadIdx.x == 0) g_vq = 0.f;
    }
}

// ---------------- bf16 mma.sync GEMM: C[M,N] = A[M,K] * B[N,K]^T ---------------
// Block 128x256, 8 warps (2m x 4n), warp tile 64x64, K-chunk 32, double buffer.
// smem pitch = 40 bf16 (80B): conflict-free 32-bit fragment loads.
// EPI=0: fp32 C. EPI=1: +bias, fp32 C, and bf16 [hi|hi|lo] split rows into Csplit.
#define SM_PITCH 40
#define A_BYTES  (128 * SM_PITCH * 2)    // 10240
#define B_BYTES  (256 * SM_PITCH * 2)    // 20480
#define STAGE    (A_BYTES + B_BYTES)     // 30720
#define GEMM_SMEM (2 * STAGE)            // 61440

template<int KCH, int EPI>
__global__ void __launch_bounds__(256)
tc_gemm(const __nv_bfloat16* __restrict__ A, int lda,
        const __nv_bfloat16* __restrict__ B, int ldb,
        const float* __restrict__ bias,
        float* __restrict__ C, int ldc,
        __nv_bfloat16* __restrict__ Csplit) {
    extern __shared__ __align__(128) char smem[];
    const int tid  = threadIdx.x;
    const int wid  = tid >> 5;
    const int lane = tid & 31;
    const int g    = lane >> 2;      // 0..7
    const int t    = lane & 3;       // 0..3
    const int wm   = wid & 1;        // 0..1
    const int wn   = wid >> 1;       // 0..3
    const int row0 = blockIdx.y * 128;
    const int col0 = blockIdx.x * 256;

    float acc[4][8][4];
    #pragma unroll
    for (int mi = 0; mi < 4; mi++)
        #pragma unroll
        for (int nj = 0; nj < 8; nj++)
            #pragma unroll
            for (int q = 0; q < 4; q++) acc[mi][nj][q] = 0.f;

    auto do_copy = [&](int c, int s) {
        char* sA = smem + s * STAGE;
        char* sB = sA + A_BYTES;
        const int k0 = c * 32;
        #pragma unroll
        for (int i = 0; i < 6; i++) {
            int tt = tid + 256 * i;
            if (tt < 512) {                       // A: 128 rows x 4 x 16B
                int r = tt >> 2, kc = tt & 3;
                cp16(sA + r * (SM_PITCH * 2) + kc * 16,
                     A + (size_t)(row0 + r) * lda + k0 + kc * 8);
            } else {                              // B: 256 rows x 4 x 16B
                int u = tt - 512;
                int r = u >> 2, kc = u & 3;
                cp16(sB + r * (SM_PITCH * 2) + kc * 16,
                     B + (size_t)(col0 + r) * ldb + k0 + kc * 8);
            }
        }
        cp_commit();
    };

    do_copy(0, 0);
    for (int c = 0; c < KCH; c++) {
        const int s = c & 1;
        if (c + 1 < KCH) {
            do_copy(c + 1, s ^ 1);
            asm volatile("cp.async.wait_group 1;" ::: "memory");
        } else {
            asm volatile("cp.async.wait_group 0;" ::: "memory");
        }
        __syncthreads();

        const char* sA = smem + s * STAGE;
        const char* sB = sA + A_BYTES;
        #pragma unroll
        for (int k16 = 0; k16 < 2; k16++) {
            const int kc = k16 * 16 + t * 2;
            uint32_t af[4][4];
            #pragma unroll
            for (int mi = 0; mi < 4; mi++) {
                int row = wm * 64 + mi * 16 + g;
                af[mi][0] = *(const uint32_t*)(sA + (row * SM_PITCH + kc) * 2);
                af[mi][1] = *(const uint32_t*)(sA + ((row + 8) * SM_PITCH + kc) * 2);
                af[mi][2] = *(const uint32_t*)(sA + (row * SM_PITCH + kc + 8) * 2);
                af[mi][3] = *(const uint32_t*)(sA + ((row + 8) * SM_PITCH + kc + 8) * 2);
            }
            #pragma unroll
            for (int nj = 0; nj < 8; nj++) {
                int n = wn * 64 + nj * 8 + g;
                uint32_t b0 = *(const uint32_t*)(sB + (n * SM_PITCH + kc) * 2);
                uint32_t b1 = *(const uint32_t*)(sB + (n * SM_PITCH + kc + 8) * 2);
                #pragma unroll
                for (int mi = 0; mi < 4; mi++)
                    mma16816(acc[mi][nj], af[mi], b0, b1);
            }
        }
        __syncthreads();
    }

    // epilogue
    #pragma unroll
    for (int mi = 0; mi < 4; mi++) {
        #pragma unroll
        for (int nj = 0; nj < 8; nj++) {
            const float* cr = acc[mi][nj];
            int row = row0 + wm * 64 + mi * 16 + g;
            int col = col0 + wn * 64 + nj * 8 + t * 2;
            if (EPI == 0) {
                *(float2*)(C + (size_t)row * ldc + col)       = make_float2(cr[0], cr[1]);
                *(float2*)(C + (size_t)(row + 8) * ldc + col) = make_float2(cr[2], cr[3]);
            } else {
                float bx = bias[col], by = bias[col + 1];
                float v0 = cr[0] + bx, v1 = cr[1] + by;
                float v2 = cr[2] + bx, v3 = cr[3] + by;
                *(float2*)(C + (size_t)row * ldc + col)       = make_float2(v0, v1);
                *(float2*)(C + (size_t)(row + 8) * ldc + col) = make_float2(v2, v3);
                __nv_bfloat16 h0, l0, h1, l1, h2, l2, h3, l3;
                split2(v0, h0, l0); split2(v1, h1, l1);
                split2(v2, h2, l2); split2(v3, h3, l3);
                __nv_bfloat162 hp0 = {h0, h1}, lp0 = {l0, l1};
                __nv_bfloat162 hp1 = {h2, h3}, lp1 = {l2, l3};
                __nv_bfloat16* d0 = Csplit + (size_t)row * 1536 + col;
                __nv_bfloat16* d1 = Csplit + (size_t)(row + 8) * 1536 + col;
                *(__nv_bfloat162*)(d0)        = hp0;
                *(__nv_bfloat162*)(d0 + 512)  = hp0;
                *(__nv_bfloat162*)(d0 + 1024) = lp0;
                *(__nv_bfloat162*)(d1)        = hp1;
                *(__nv_bfloat162*)(d1 + 512)  = hp1;
                *(__nv_bfloat162*)(d1 + 1024) = lp1;
            }
        }
    }
}

// ---------------- per-row: approx select -> exact refine -> outputs ------------
__global__ void __launch_bounds__(256)
topk_kernel(const float* __restrict__ embed, float* __restrict__ out) {
    int w = threadIdx.x >> 5, lane = threadIdx.x & 31;
    int r = blockIdx.x * 8 + w;

    const float4* zr4 = (const float4*)(g_z + (size_t)r * DB);
    float4 zreg[4];
    float zn = 0.f;
    #pragma unroll
    for (int i = 0; i < 4; i++) {
        float4 v = zr4[lane + 32 * i];
        zreg[i] = v;
        zn += v.x * v.x + v.y * v.y + v.z * v.z + v.w * v.w;
    }
    #pragma unroll
    for (int o = 16; o; o >>= 1) zn += __shfl_xor_sync(0xffffffffu, zn, o);

    // --- approx per-lane top-KSEL over d2_approx ---
    float td[KSEL]; int ti[KSEL];
    #pragma unroll
    for (int j = 0; j < KSEL; j++) { td[j] = FLT_MAX; ti[j] = 0x7fffffff; }

    auto insert = [&](float dv, int iv) {
        if (dv < td[KSEL - 1]) {
            #pragma unroll
            for (int j = KSEL - 1; j >= 0; j--) {
                bool shift = (j > 0) && (td[j - 1] > dv);
                if (shift) { td[j] = td[j - 1]; ti[j] = ti[j - 1]; }
                else       { td[j] = dv; ti[j] = iv; break; }
            }
        }
    };

    const float4* Sr4 = (const float4*)(g_S + (size_t)r * NC);
    const float4* en4 = (const float4*)g_enorm;
    #pragma unroll
    for (int it = 0; it < 8; it++) {
        int idx = lane + 32 * it;
        float4 s4 = Sr4[idx];
        float4 e4 = en4[idx];
        int c0 = idx * 4;
        insert(zn + e4.x - 2.f * s4.x, c0 + 0);
        insert(zn + e4.y - 2.f * s4.y, c0 + 1);
        insert(zn + e4.z - 2.f * s4.z, c0 + 2);
        insert(zn + e4.w - 2.f * s4.w, c0 + 3);
    }

    // --- warp merge to KSEL approx candidates (broadcast to all lanes) ---
    int ci[KSEL];
    int pos = 0;
    #pragma unroll
    for (int j = 0; j < KSEL; j++) {
        float cd = (pos < KSEL) ? td[pos] : FLT_MAX;
        int   cc = (pos < KSEL) ? ti[pos] : 0x7fffffff;
        float bd = cd; int bi = cc; int bl = lane;
        #pragma unroll
        for (int o = 16; o; o >>= 1) {
            float od = __shfl_xor_sync(0xffffffffu, bd, o);
            int   oi = __shfl_xor_sync(0xffffffffu, bi, o);
            int   ol = __shfl_xor_sync(0xffffffffu, bl, o);
            if (od < bd || (od == bd && oi < bi)) { bd = od; bi = oi; bl = ol; }
        }
        ci[j] = bi;
        if (lane == bl) pos++;
    }

    // --- exact fp32 refine: d2 = ||z||^2 + ||e||^2 - 2 z.e ---
    float xd[KSEL];
    #pragma unroll
    for (int j = 0; j < KSEL; j++) {
        const float4* ev = (const float4*)(embed + (size_t)ci[j] * DB);
        float dot = 0.f;
        #pragma unroll
        for (int i = 0; i < 4; i++) {
            float4 f = ev[lane + 32 * i];
            dot += zreg[i].x * f.x + zreg[i].y * f.y
                 + zreg[i].z * f.z + zreg[i].w * f.w;
        }
        #pragma unroll
        for (int o = 16; o; o >>= 1) dot += __shfl_xor_sync(0xffffffffu, dot, o);
        xd[j] = zn + g_enorm[ci[j]] - 2.f * dot;
    }

    // --- bubble sort (compile-time indices, all lanes identical) ---
    #pragma unroll
    for (int a = 0; a < KSEL - 1; a++) {
        #pragma unroll
        for (int b = 0; b < KSEL - 1 - a; b++) {
            bool sw = (xd[b + 1] < xd[b]) ||
                      (xd[b + 1] == xd[b] && ci[b + 1] < ci[b]);
            if (sw) {
                float tf = xd[b]; xd[b] = xd[b + 1]; xd[b + 1] = tf;
                int   tn = ci[b]; ci[b] = ci[b + 1]; ci[b + 1] = tn;
            }
        }
    }

    // --- softmax over exact sqrt(d2) of top-8 ---
    float wj[KTOP];
    float vmin = sqrtf(fmaxf(xd[0], 0.f));
    float wsum = 0.f;
    #pragma unroll
    for (int j = 0; j < KTOP; j++) {
        float v = sqrtf(fmaxf(xd[j], 0.f));
        wj[j] = expf(-(v - vmin) / TEMP);
        wsum += wj[j];
    }
    float inv = 1.f / wsum;
    #pragma unroll
    for (int j = 0; j < KTOP; j++) wj[j] *= inv;

    // --- q gather + vq partial ---
    float vql = 0.f;
    #pragma unroll
    for (int i = 0; i < 4; i++) {
        int c4 = lane + 32 * i;
        float4 a = make_float4(0.f, 0.f, 0.f, 0.f);
        #pragma unroll
        for (int j = 0; j < KTOP; j++) {
            const float4* ev = (const float4*)(embed + (size_t)ci[j] * DB);
            float4 f = ev[c4];
            a.x += wj[j] * f.x; a.y += wj[j] * f.y;
            a.z += wj[j] * f.z; a.w += wj[j] * f.w;
        }
        ((float4*)(out + (size_t)r * DB))[c4] = a;
        float dx = zreg[i].x - a.x, dy = zreg[i].y - a.y;
        float dz = zreg[i].z - a.z, dw = zreg[i].w - a.w;
        vql += dx * dx + dy * dy + dz * dz + dw * dw;
    }
    #pragma unroll
    for (int o = 16; o; o >>= 1) vql += __shfl_down_sync(0xffffffffu, vql, o);
    if (lane == 0) atomicAdd(&g_vq, vql);
    if (lane < KTOP) atomicAdd(&g_usage[ci[lane]], wj[lane]);
    if (lane == 0) out[(size_t)NROWS * DB + r] = (float)ci[0];
}

// ---------------- finalize scalars --------------------------------------------
__global__ void finalize_kernel(float* __restrict__ out) {
    __shared__ float sh[256];
    float s = 0.f;
    for (int c = threadIdx.x; c < NC; c += 256) {
        float u = g_usage[c] * (1.f / (float)NROWS);
        s += u * logf(u + 1e-8f);
    }
    sh[threadIdx.x] = s;
    __syncthreads();
    for (int o = 128; o; o >>= 1) {
        if (threadIdx.x < o) sh[threadIdx.x] += sh[threadIdx.x + o];
        __syncthreads();
    }
    if (threadIdx.x == 0) {
        size_t base = (size_t)NROWS * DB + NROWS;
        out[base + 0] = g_vq * (1.f / (float)((size_t)NROWS * DB));
        out[base + 1] = -sh[0];
    }
}

// ---------------- launch --------------------------------------------------------
extern "C" void kernel_launch(void* const* d_in, const int* in_sizes, int n_in,
                              void* d_out, int out_size) {
    const float* slots = (const float*)d_in[0];
    const float* W     = (const float*)d_in[1];
    const float* bias  = (const float*)d_in[2];
    const float* embed = (const float*)d_in[3];
    float* out = (float*)d_out;

    float *zp = nullptr, *Sp = nullptr;
    __nv_bfloat16 *asp = nullptr, *wbp = nullptr, *zsp = nullptr, *ebp = nullptr;
    cudaGetSymbolAddress((void**)&zp,  g_z);
    cudaGetSymbolAddress((void**)&Sp,  g_S);
    cudaGetSymbolAddress((void**)&asp, g_as);
    cudaGetSymbolAddress((void**)&wbp, g_wb);
    cudaGetSymbolAddress((void**)&zsp, g_zs);
    cudaGetSymbolAddress((void**)&ebp, g_eb);

    cudaFuncSetAttribute(tc_gemm<48, 1>,
                         cudaFuncAttributeMaxDynamicSharedMemorySize, GEMM_SMEM);
    cudaFuncSetAttribute(tc_gemm<48, 0>,
                         cudaFuncAttributeMaxDynamicSharedMemorySize, GEMM_SMEM);

    split_slots_kernel<<<(NROWS * D_IN) / 256, 256>>>(slots);
    split_w_kernel<<<(D_IN * DB) / 256, 256>>>(W);
    init_kernel<<<128, 256>>>(embed);

    // z = slots @ W + b : A'=[16384,1536], B'=[512,1536] -> fp32 z + split z
    tc_gemm<48, 1><<<dim3(2, 128), 256, GEMM_SMEM>>>(
        asp, 1536, wbp, 1536, bias, zp, 512, zsp);

    // S ~= z @ E^T : A'=[16384,1536], B'=[1024,1536] -> approx fp32 S
    tc_gemm<48, 0><<<dim3(4, 128), 256, GEMM_SMEM>>>(
        zsp, 1536, ebp, 1536, nullptr, Sp, 1024, nullptr);

    topk_kernel<<<NROWS / 8, 256>>>(embed, out);
    finalize_kernel<<<1, 256>>>(out);
}